// round 15
// baseline (speedup 1.0000x reference)
#include <cuda_runtime.h>
#include <cuda_fp16.h>
#include <cstdint>
#include <math.h>

#define BB 2
#define NN 256
#define NODE_DIM 128
#define EDGE_DIM 256
#define HID 256
#define HH 8
#define DD 32
#define LN_EPS 1e-5f
#define OUT_EDGE_BASE (BB*NN*HID)

// Eh block distribution across the three prologue kernels
#define NEH1 3000
#define NEH2 3000
#define NEH3 2192

// ---------------- scratch (device globals) ----------------------------------
__device__ __align__(16) float d_h [BB*NN*HID];
__device__ __align__(16) float d_q [BB*NN*HID];
__device__ __align__(16) float d_k [BB*NN*HID];
__device__ __align__(16) float d_v [BB*NN*HID];
__device__ __align__(16) float d_scores[BB*HH*NN*NN];
__device__ __align__(16) float d_am[BB*NN*NN];
__device__ __align__(16) float d_ao[BB*NN*HID];
__device__ __align__(16) float d_hp[BB*NN*HID];
__device__ __align__(16) __half d_Eh  [BB*NN*NN*EDGE_DIM];
__device__ __align__(16) __half d_WpTh[HID*EDGE_DIM];
__device__ __align__(16) __half d_WgTh[HID*EDGE_DIM];

// ---------------- PTX helpers ------------------------------------------------
__device__ __forceinline__ uint32_t smem_u32(const void* p) {
    uint32_t a;
    asm("{ .reg .u64 t; cvta.to.shared.u64 t, %1; cvt.u32.u64 %0, t; }" : "=r"(a) : "l"(p));
    return a;
}
__device__ __forceinline__ void cp_async16(uint32_t dst, const void* src) {
    asm volatile("cp.async.cg.shared.global [%0], [%1], 16;" :: "r"(dst), "l"(src));
}
#define CP_COMMIT() asm volatile("cp.async.commit_group;" ::: "memory")
#define CP_WAIT(n)  asm volatile("cp.async.wait_group %0;" :: "n"(n) : "memory")

__device__ __forceinline__ void mma_f16(float d[4], uint32_t a0, uint32_t a1,
                                        uint32_t a2, uint32_t a3,
                                        uint32_t b0, uint32_t b1) {
    asm volatile(
        "mma.sync.aligned.m16n8k16.row.col.f32.f16.f16.f32 "
        "{%0,%1,%2,%3}, {%4,%5,%6,%7}, {%8,%9}, {%0,%1,%2,%3};"
        : "+f"(d[0]), "+f"(d[1]), "+f"(d[2]), "+f"(d[3])
        : "r"(a0), "r"(a1), "r"(a2), "r"(a3), "r"(b0), "r"(b1));
}
__device__ __forceinline__ uint32_t packh2(float a, float b) {
    __half2 h = __float22half2_rn(make_float2(a, b));
    return *(uint32_t*)&h;
}

// E -> packed fp16 slice (one "block" worth, index eb in [0, 8192))
__device__ __forceinline__ void eh_block(const float* __restrict__ E, int eb) {
    size_t t = (size_t)eb * 256 + threadIdx.x;
    const float4* s = (const float4*)E + t * 4;
    float4 v0 = s[0], v1 = s[1], v2 = s[2], v3 = s[3];
    uint4 o0, o1;
    o0.x = packh2(v0.x, v0.y);
    o0.y = packh2(v2.x, v2.y);
    o0.z = packh2(v0.z, v0.w);
    o0.w = packh2(v2.z, v2.w);
    o1.x = packh2(v1.x, v1.y);
    o1.y = packh2(v3.x, v3.y);
    o1.z = packh2(v1.z, v1.w);
    o1.w = packh2(v3.z, v3.w);
    uint4* d = (uint4*)d_Eh + t * 2;
    d[0] = o0; d[1] = o1;
}

// ---------------- 0a. weight transpose + fp16 pack ---------------------------
__global__ void k_wT(const float* __restrict__ Wep, const float* __restrict__ Weg) {
    __shared__ float t[32][33];
    const float* W = blockIdx.z ? Weg : Wep;
    __half* O = blockIdx.z ? d_WgTh : d_WpTh;
    int n0 = blockIdx.x * 32, k0 = blockIdx.y * 32;
    t[threadIdx.y][threadIdx.x] = W[(k0 + threadIdx.y) * EDGE_DIM + n0 + threadIdx.x];
    __syncthreads();
    float v = t[threadIdx.x][threadIdx.y];
    int k = k0 + threadIdx.x;
    int kk = k & 15;
    int pos = (((kk & 7) >> 1) * 2 + ((kk >> 3) & 1)) * 2 + (kk & 1);
    O[(n0 + threadIdx.y) * EDGE_DIM + (k & ~15) + pos] = __float2half_rn(v);
}

// ---------------- 1. node_proj (+Eh slice) -----------------------------------
#define SM_NP ((NODE_DIM*4 + 2*32*HID)*4)
__global__ void __launch_bounds__(256)
k_node_f(const float* __restrict__ node, const float* __restrict__ Wn,
         const float* __restrict__ bn, const float* __restrict__ E) {
    if (blockIdx.x >= BB*NN/4) { eh_block(E, blockIdx.x - BB*NN/4); return; }
    extern __shared__ float sm[];
    float* st = sm;                    // [128][4] transposed staging
    float* sW = sm + NODE_DIM*4;       // [2][32][256]
    uint32_t wb = smem_u32(sW);
    int tid = threadIdx.x;
    int r0 = blockIdx.x * 4;
    for (int i = tid; i < 4 * NODE_DIM; i += 256) {
        int r = i >> 7, k = i & 127;
        st[k * 4 + r] = node[(r0 + r) * NODE_DIM + k];
    }
    #pragma unroll
    for (int i = 0; i < 8; ++i) {
        int lin = tid + i * 256;
        int row = lin >> 6, c4 = (lin & 63) * 4;
        cp_async16(wb + (row * 256 + c4) * 4, &Wn[row * HID + c4]);
    }
    CP_COMMIT();
    int c = tid;
    float acc[4]; float bb = bn[c];
    #pragma unroll
    for (int r = 0; r < 4; ++r) acc[r] = bb;
    #pragma unroll 1
    for (int t = 0; t < 4; ++t) {
        int buf = t & 1;
        if (t < 3) {
            int nb = buf ^ 1;
            #pragma unroll
            for (int i = 0; i < 8; ++i) {
                int lin = tid + i * 256;
                int row = lin >> 6, c4 = (lin & 63) * 4;
                cp_async16(wb + ((nb * 32 + row) * 256 + c4) * 4,
                           &Wn[((t + 1) * 32 + row) * HID + c4]);
            }
            CP_COMMIT(); CP_WAIT(1);
        } else CP_WAIT(0);
        __syncthreads();
        const float* Wt = sW + buf * 32 * 256;
        #pragma unroll
        for (int k = 0; k < 32; ++k) {
            float w = Wt[k * 256 + c];
            float4 sv = *(const float4*)&st[(t * 32 + k) * 4];
            acc[0] += sv.x * w; acc[1] += sv.y * w;
            acc[2] += sv.z * w; acc[3] += sv.w * w;
        }
        __syncthreads();
    }
    #pragma unroll
    for (int r = 0; r < 4; ++r) d_h[(r0 + r) * HID + c] = acc[r];
}

// ---------------- 2. Q,K,V (+Eh slice) ---------------------------------------
#define SM_GEMM ((HID*4 + 2*32*HID)*4)
__global__ void __launch_bounds__(256)
k_qkv_f(const float* __restrict__ Wq, const float* __restrict__ bq,
        const float* __restrict__ Wk, const float* __restrict__ bk,
        const float* __restrict__ Wv, const float* __restrict__ bv,
        const float* __restrict__ E) {
    if (blockIdx.x >= 3*BB*NN/4) { eh_block(E, NEH1 + blockIdx.x - 3*BB*NN/4); return; }
    extern __shared__ float sm[];
    float* st = sm;                  // [256][4]
    float* sW = sm + HID*4;          // [2][32][256]
    uint32_t wb = smem_u32(sW);
    int z = blockIdx.x / (BB*NN/4);
    int rb = blockIdx.x % (BB*NN/4);
    const float* W  = (z == 0) ? Wq : (z == 1) ? Wk : Wv;
    const float* bi = (z == 0) ? bq : (z == 1) ? bk : bv;
    float* O        = (z == 0) ? d_q : (z == 1) ? d_k : d_v;
    int tid = threadIdx.x;
    int r0 = rb * 4;
    for (int i = tid; i < 4 * HID; i += 256) {
        int r = i >> 8, k = i & 255;
        st[k * 4 + r] = d_h[(r0 + r) * HID + k];
    }
    #pragma unroll
    for (int i = 0; i < 8; ++i) {
        int lin = tid + i * 256;
        int row = lin >> 6, c4 = (lin & 63) * 4;
        cp_async16(wb + (row * 256 + c4) * 4, &W[row * HID + c4]);
    }
    CP_COMMIT();
    int c = tid;
    float acc[4]; float bb = bi[c];
    #pragma unroll
    for (int r = 0; r < 4; ++r) acc[r] = bb;
    #pragma unroll 1
    for (int t = 0; t < 8; ++t) {
        int buf = t & 1;
        if (t < 7) {
            int nb = buf ^ 1;
            #pragma unroll
            for (int i = 0; i < 8; ++i) {
                int lin = tid + i * 256;
                int row = lin >> 6, c4 = (lin & 63) * 4;
                cp_async16(wb + ((nb * 32 + row) * 256 + c4) * 4,
                           &W[((t + 1) * 32 + row) * HID + c4]);
            }
            CP_COMMIT(); CP_WAIT(1);
        } else CP_WAIT(0);
        __syncthreads();
        const float* Wt = sW + buf * 32 * 256;
        #pragma unroll
        for (int k = 0; k < 32; ++k) {
            float w = Wt[k * 256 + c];
            float4 sv = *(const float4*)&st[(t * 32 + k) * 4];
            acc[0] += sv.x * w; acc[1] += sv.y * w;
            acc[2] += sv.z * w; acc[3] += sv.w * w;
        }
        __syncthreads();
    }
    #pragma unroll
    for (int r = 0; r < 4; ++r) O[(r0 + r) * HID + c] = acc[r];
}

// ---------------- 3. scores (+Eh slice) --------------------------------------
#define KS_PAD 36
__global__ void k_scores_f(const float* __restrict__ E) {
    if (blockIdx.x >= BB*HH*4) { eh_block(E, NEH1 + NEH2 + blockIdx.x - BB*HH*4); return; }
    int nt = blockIdx.x & 3;
    int h  = (blockIdx.x >> 2) & 7;
    int b  = blockIdx.x >> 5;
    __shared__ float sQ[64][KS_PAD];
    __shared__ float sK[256][KS_PAD];
    int tid = threadIdx.x;
    #pragma unroll
    for (int i = 0; i < 32; ++i) {
        int idx = tid + i * 256;
        int r = idx >> 5, c = idx & 31;
        sK[r][c] = d_k[(b * NN + r) * HID + h * DD + c];
    }
    #pragma unroll
    for (int i = 0; i < 8; ++i) {
        int idx = tid + i * 256;
        int r = idx >> 5, c = idx & 31;
        sQ[r][c] = d_q[(b * NN + nt * 64 + r) * HID + h * DD + c];
    }
    __syncthreads();
    int nl = tid >> 2, q = tid & 3;
    float qr[32];
    #pragma unroll
    for (int d = 0; d < 32; ++d) qr[d] = sQ[nl][d];
    float* dst = &d_scores[(((size_t)b * HH + h) * NN + nt * 64 + nl) * NN];
    #pragma unroll 4
    for (int i = 0; i < 64; ++i) {
        int m = i * 4 + q;
        float acc = 0.f;
        #pragma unroll
        for (int d = 0; d < 32; ++d) acc += qr[d] * sK[m][d];
        dst[m] = acc * 0.17677669529663687f;
    }
}

// ---------------- 4. edge bias GEMM + fused masked softmax --------------------
#define SA_STRIDE_H 40
#define SA_BUF_H    (256*SA_STRIDE_H)
#define OFF_BP_H    (2*SA_BUF_H)
#define SB_STRIDE_H 264
#define OFF_BG_H    (OFF_BP_H + 32*SB_STRIDE_H)
#define OFF_BIAS_H  (OFF_BG_H + 32*SB_STRIDE_H)
#define SMEM_BYTES  (OFF_BIAS_H*2 + (64+256+256)*4)

__global__ void __launch_bounds__(256, 2)
k_edge_attn_mma(const float* __restrict__ bep, const float* __restrict__ beg,
                const int* __restrict__ adj) {
    extern __shared__ __half smh[];
    const int tid = threadIdx.x;
    const int wid = tid >> 5, lane = tid & 31;
    const int tig = lane & 3, grp = lane >> 2;
    const int h = blockIdx.x;
    const int row0 = blockIdx.y * 256;

    __half* sBp = smh + OFF_BP_H;
    __half* sBg = smh + OFF_BG_H;
    float* sbias = (float*)(smh + OFF_BIAS_H);
    float* sRow  = sbias + 64;
    float* sRed  = sRow + 256;
    uint32_t sA_addr = smem_u32(smh);

    #pragma unroll
    for (int i = 0; i < 4; ++i) {
        int lin = tid + i * 256;
        int n = lin >> 5, q = lin & 31;
        *(uint4*)&sBp[n * SB_STRIDE_H + q * 8] =
            *(const uint4*)&d_WpTh[(h * 32 + n) * EDGE_DIM + q * 8];
        *(uint4*)&sBg[n * SB_STRIDE_H + q * 8] =
            *(const uint4*)&d_WgTh[(h * 32 + n) * EDGE_DIM + q * 8];
    }
    if (tid < 32) {
        sbias[tid]      = bep[h * 32 + tid];
        sbias[32 + tid] = beg[h * 32 + tid];
    }

    float d[2][8][4];
    #pragma unroll
    for (int m = 0; m < 2; ++m)
        #pragma unroll
        for (int j = 0; j < 8; ++j)
            #pragma unroll
            for (int e = 0; e < 4; ++e) d[m][j][e] = 0.f;

    #pragma unroll
    for (int i = 0; i < 4; ++i) {
        int lin = tid + i * 256;
        int r = lin >> 2, q = lin & 3;
        cp_async16(sA_addr + (r * SA_STRIDE_H + q * 8) * 2,
                   &d_Eh[(size_t)(row0 + r) * EDGE_DIM + q * 8]);
    }
    CP_COMMIT();

    #pragma unroll 1
    for (int c = 0; c < 8; ++c) {
        int buf = c & 1;
        if (c < 7) {
            int nb = buf ^ 1;
            #pragma unroll
            for (int i = 0; i < 4; ++i) {
                int lin = tid + i * 256;
                int r = lin >> 2, q = lin & 3;
                cp_async16(sA_addr + (nb * SA_BUF_H + r * SA_STRIDE_H + q * 8) * 2,
                           &d_Eh[(size_t)(row0 + r) * EDGE_DIM + (c + 1) * 32 + q * 8]);
            }
            CP_COMMIT();
            CP_WAIT(1);
        } else {
            CP_WAIT(0);
        }
        __syncthreads();

        const __half* Ab = smh + buf * SA_BUF_H + (wid * 32) * SA_STRIDE_H;
        #pragma unroll
        for (int t = 0; t < 2; ++t) {
            uint2 alo[2], ahi[2];
            #pragma unroll
            for (int m = 0; m < 2; ++m) {
                alo[m] = *(const uint2*)&Ab[(m * 16 + grp) * SA_STRIDE_H + t * 16 + tig * 4];
                ahi[m] = *(const uint2*)&Ab[(m * 16 + grp + 8) * SA_STRIDE_H + t * 16 + tig * 4];
            }
            int kb = c * 32 + t * 16 + tig * 4;
            #pragma unroll
            for (int j = 0; j < 8; ++j) {
                const __half* Bm = (j < 4) ? sBp : sBg;
                uint2 bb = *(const uint2*)&Bm[((j & 3) * 8 + grp) * SB_STRIDE_H + kb];
                mma_f16(d[0][j], alo[0].x, ahi[0].x, alo[0].y, ahi[0].y, bb.x, bb.y);
                mma_f16(d[1][j], alo[1].x, ahi[1].x, alo[1].y, ahi[1].y, bb.x, bb.y);
            }
        }
        __syncthreads();
    }

    #pragma unroll
    for (int m = 0; m < 2; ++m) {
        float s0 = 0.f, s1 = 0.f;
        #pragma unroll
        for (int j = 0; j < 4; ++j) {
            #pragma unroll
            for (int e = 0; e < 2; ++e) {
                int cl = j * 8 + tig * 2 + e;
                float bp = sbias[cl], bg = sbias[32 + cl];
                float p0 = d[m][j][e]     + bp;
                float g0 = d[m][j + 4][e] + bg;
                s0 += p0 / (1.f + expf(-g0));
                float p1 = d[m][j][e + 2]     + bp;
                float g1 = d[m][j + 4][e + 2] + bg;
                s1 += p1 / (1.f + expf(-g1));
            }
        }
        s0 += __shfl_xor_sync(0xffffffffu, s0, 1);
        s0 += __shfl_xor_sync(0xffffffffu, s0, 2);
        s1 += __shfl_xor_sync(0xffffffffu, s1, 1);
        s1 += __shfl_xor_sync(0xffffffffu, s1, 2);
        if (tig == 0) {
            sRow[wid * 32 + m * 16 + grp]     = s0;
            sRow[wid * 32 + m * 16 + grp + 8] = s1;
        }
    }
    __syncthreads();

    {
        int n = blockIdx.y & 255, b = blockIdx.y >> 8;
        size_t base = (((size_t)b * HH + h) * NN + n) * NN;
        float sc = sRow[tid] + d_scores[base + tid];
        if (adj[(b * NN + n) * NN + tid] == 0) sc = -1e9f;
        sRed[tid] = sc; __syncthreads();
        for (int s = 128; s > 0; s >>= 1) {
            if (tid < s) sRed[tid] = fmaxf(sRed[tid], sRed[tid + s]);
            __syncthreads();
        }
        float mx = sRed[0]; __syncthreads();
        float e = expf(sc - mx);
        sRed[tid] = e; __syncthreads();
        for (int s = 128; s > 0; s >>= 1) {
            if (tid < s) sRed[tid] += sRed[tid + s];
            __syncthreads();
        }
        d_scores[base + tid] = e / sRed[0];
    }
}

// ---------------- 6+7. attn_out (2 rows/block) + fused head-mean --------------
__global__ void k_attn_out() {
    int blk = blockIdx.x;                 // 256 blocks: b*128 + nt
    int b = blk >> 7;
    int n0 = (blk & 127) * 2;
    __shared__ float sA[2][HH][NN];       // 16KB
    for (int i = threadIdx.x; i < 2 * HH * NN; i += 256) {
        int r = i >> 11, h = (i >> 8) & 7, m = i & 255;
        sA[r][h][m] = d_scores[(((size_t)b * HH + h) * NN + n0 + r) * NN + m];
    }
    __syncthreads();
    for (int i = threadIdx.x; i < 2 * NN; i += 256) {
        int r = i >> 8, m = i & 255;
        float s = 0.f;
        #pragma unroll
        for (int h2 = 0; h2 < HH; ++h2) s += sA[r][h2][m];
        d_am[(b * NN + n0 + r) * NN + m] = s * (1.f / HH);
    }
    int c = threadIdx.x;
    int h = c >> 5;
    float acc[2] = {0.f, 0.f};
    #pragma unroll 8
    for (int m = 0; m < NN; ++m) {
        float v = d_v[(b * NN + m) * HID + c];
        acc[0] += sA[0][h][m] * v;
        acc[1] += sA[1][h][m] * v;
    }
    d_ao[(b * NN + n0) * HID + c]     = acc[0];
    d_ao[(b * NN + n0 + 1) * HID + c] = acc[1];
}

// ---------------- 8+9. h_out = LN(...) then hp = h_out @ Weo ------------------
#define SM_HOUT ((HID*4 + 2*32*HID + 4*260 + 16)*4)
__global__ void __launch_bounds__(256)
k_hout_hp(const float* __restrict__ Wo, const float* __restrict__ bo,
          const float* __restrict__ g1, const float* __restrict__ b1,
          const float* __restrict__ Weo, float* __restrict__ out) {
    extern __shared__ float sm[];
    float* st  = sm;                       // [256][4] transposed staging
    float* sW  = sm + HID*4;               // [2][32][256]
    float* sy  = sW + 2*32*HID;            // [4][260]
    float* prt = sy + 4*260;               // [16]
    uint32_t wb = smem_u32(sW);
    int tid = threadIdx.x;
    int wid = tid >> 5, lane = tid & 31;
    int r0 = blockIdx.x * 4;
    for (int i = tid; i < 4 * HID; i += 256) {
        int r = i >> 8, k = i & 255;
        st[k * 4 + r] = d_ao[(r0 + r) * HID + k];
    }
    #pragma unroll
    for (int i = 0; i < 8; ++i) {
        int lin = tid + i * 256;
        int row = lin >> 6, c4 = (lin & 63) * 4;
        cp_async16(wb + (row * 256 + c4) * 4, &Wo[row * HID + c4]);
    }
    CP_COMMIT();
    int c = tid;
    float acc[4]; float bb = bo[c];
    #pragma unroll
    for (int r = 0; r < 4; ++r) acc[r] = bb;
    #pragma unroll 1
    for (int t = 0; t < 8; ++t) {
        int buf = t & 1;
        if (t < 7) {
            int nb = buf ^ 1;
            #pragma unroll
            for (int i = 0; i < 8; ++i) {
                int lin = tid + i * 256;
                int row = lin >> 6, c4 = (lin & 63) * 4;
                cp_async16(wb + ((nb * 32 + row) * 256 + c4) * 4,
                           &Wo[((t + 1) * 32 + row) * HID + c4]);
            }
            CP_COMMIT(); CP_WAIT(1);
        } else CP_WAIT(0);
        __syncthreads();
        const float* Wt = sW + buf * 32 * 256;
        #pragma unroll
        for (int k = 0; k < 32; ++k) {
            float w = Wt[k * 256 + c];
            float4 sv = *(const float4*)&st[(t * 32 + k) * 4];
            acc[0] += sv.x * w; acc[1] += sv.y * w;
            acc[2] += sv.z * w; acc[3] += sv.w * w;
        }
        __syncthreads();
    }
    #pragma unroll
    for (int r = 0; r < 4; ++r)
        sy[r * 260 + c] = acc[r] + d_h[(r0 + r) * HID + c];
    __syncthreads();
    {
        int rw = wid >> 1, off = (wid & 1) * 128;
        float ps = 0.f, ps2 = 0.f;
        #pragma unroll
        for (int j = 0; j < 4; ++j) {
            float v = sy[rw * 260 + off + j * 32 + lane];
            ps += v; ps2 += v * v;
        }
        #pragma unroll
        for (int o = 16; o > 0; o >>= 1) {
            ps  += __shfl_xor_sync(0xffffffffu, ps,  o);
            ps2 += __shfl_xor_sync(0xffffffffu, ps2, o);
        }
        if (lane == 0) { prt[wid] = ps; prt[8 + wid] = ps2; }
    }
    __syncthreads();
    float gg = g1[c], bb1 = b1[c];
    #pragma unroll
    for (int r = 0; r < 4; ++r) {
        float sum  = prt[r * 2] + prt[r * 2 + 1];
        float sum2 = prt[8 + r * 2] + prt[8 + r * 2 + 1];
        float mean = sum * (1.f / HID);
        float var  = sum2 * (1.f / HID) - mean * mean;
        float y = sy[r * 260 + c];
        float o = (y - mean) * rsqrtf(var + LN_EPS) * gg + bb1;
        out[(r0 + r) * HID + c] = o;
        st[c * 4 + r] = o;                // re-stage transposed for phase 2
    }
    __syncthreads();

    // ---- phase 2: hp = h_out @ Weo ----
    #pragma unroll
    for (int i = 0; i < 8; ++i) {
        int lin = tid + i * 256;
        int row = lin >> 6, c4 = (lin & 63) * 4;
        cp_async16(wb + (row * 256 + c4) * 4, &Weo[row * EDGE_DIM + c4]);
    }
    CP_COMMIT();
    float acc2[4] = {0.f, 0.f, 0.f, 0.f};
    #pragma unroll 1
    for (int t = 0; t < 8; ++t) {
        int buf = t & 1;
        if (t < 7) {
            int nb = buf ^ 1;
            #pragma unroll
            for (int i = 0; i < 8; ++i) {
                int lin = tid + i * 256;
                int row = lin >> 6, c4 = (lin & 63) * 4;
                cp_async16(wb + ((nb * 32 + row) * 256 + c4) * 4,
                           &Weo[((t + 1) * 32 + row) * EDGE_DIM + c4]);
            }
            CP_COMMIT(); CP_WAIT(1);
        } else CP_WAIT(0);
        __syncthreads();
        const float* Wt = sW + buf * 32 * 256;
        #pragma unroll
        for (int k = 0; k < 32; ++k) {
            float w = Wt[k * 256 + c];
            float4 sv = *(const float4*)&st[(t * 32 + k) * 4];
            acc2[0] += sv.x * w; acc2[1] += sv.y * w;
            acc2[2] += sv.z * w; acc2[3] += sv.w * w;
        }
        __syncthreads();
    }
    #pragma unroll
    for (int r = 0; r < 4; ++r) d_hp[(r0 + r) * EDGE_DIM + c] = acc2[r];
}

// ---------------- 10. edge_out (float4) ---------------------------------------
__global__ void k_edge_out(const float* __restrict__ E,
                           const float* __restrict__ beo,
                           const float* __restrict__ g2,
                           const float* __restrict__ b2,
                           float* __restrict__ out) {
    int w = blockIdx.x * 8 + (threadIdx.x >> 5);
    int lane = threadIdx.x & 31;
    int m = w & 255, n = (w >> 8) & 255, b = w >> 16;
    float am = d_am[w] * 0.5f;
    const float4* Er = (const float4*)&E[(size_t)w * EDGE_DIM];
    const float4* hn = (const float4*)&d_hp[(b * NN + n) * EDGE_DIM];
    const float4* hm = (const float4*)&d_hp[(b * NN + m) * EDGE_DIM];
    const float4* bo4 = (const float4*)beo;
    float4 x[2];
    float s = 0.f, s2 = 0.f;
    #pragma unroll
    for (int j = 0; j < 2; ++j) {
        int idx = j * 32 + lane;
        float4 e = Er[idx], a = hn[idx], cc = hm[idx], bb = bo4[idx];
        float4 v;
        v.x = e.x + am * (a.x + cc.x) + bb.x;
        v.y = e.y + am * (a.y + cc.y) + bb.y;
        v.z = e.z + am * (a.z + cc.z) + bb.z;
        v.w = e.w + am * (a.w + cc.w) + bb.w;
        x[j] = v;
        s  += v.x + v.y + v.z + v.w;
        s2 += v.x*v.x + v.y*v.y + v.z*v.z + v.w*v.w;
    }
    #pragma unroll
    for (int o = 16; o > 0; o >>= 1) {
        s  += __shfl_xor_sync(0xffffffffu, s,  o);
        s2 += __shfl_xor_sync(0xffffffffu, s2, o);
    }
    float mean = s * (1.f / EDGE_DIM);
    float var  = s2 * (1.f / EDGE_DIM) - mean * mean;
    float rinv = rsqrtf(var + LN_EPS);
    const float4* g4 = (const float4*)g2;
    const float4* b4 = (const float4*)b2;
    float4* op = (float4*)&out[OUT_EDGE_BASE + (size_t)w * EDGE_DIM];
    #pragma unroll
    for (int j = 0; j < 2; ++j) {
        int idx = j * 32 + lane;
        float4 g = g4[idx], bb = b4[idx], v = x[j], o4;
        o4.x = (v.x - mean) * rinv * g.x + bb.x;
        o4.y = (v.y - mean) * rinv * g.y + bb.y;
        o4.z = (v.z - mean) * rinv * g.z + bb.z;
        o4.w = (v.w - mean) * rinv * g.w + bb.w;
        op[idx] = o4;
    }
}

// ---------------- launch ------------------------------------------------------
extern "C" void kernel_launch(void* const* d_in, const int* in_sizes, int n_in,
                              void* d_out, int out_size) {
    const float* node = (const float*)d_in[0];
    const float* E    = (const float*)d_in[1];
    const int*   adj  = (const int*)  d_in[2];
    const float* Wn  = (const float*)d_in[3];  const float* bn  = (const float*)d_in[4];
    const float* Wq  = (const float*)d_in[5];  const float* bq  = (const float*)d_in[6];
    const float* Wk  = (const float*)d_in[7];  const float* bk  = (const float*)d_in[8];
    const float* Wv  = (const float*)d_in[9];  const float* bv  = (const float*)d_in[10];
    const float* Wep = (const float*)d_in[11]; const float* bep = (const float*)d_in[12];
    const float* Weg = (const float*)d_in[13]; const float* beg = (const float*)d_in[14];
    const float* Wo  = (const float*)d_in[15]; const float* bo  = (const float*)d_in[16];
    const float* Weo = (const float*)d_in[17]; const float* beo = (const float*)d_in[18];
    const float* g1  = (const float*)d_in[19]; const float* b1  = (const float*)d_in[20];
    const float* g2  = (const float*)d_in[21]; const float* b2  = (const float*)d_in[22];
    float* out = (float*)d_out;

    cudaFuncSetAttribute(k_edge_attn_mma, cudaFuncAttributeMaxDynamicSharedMemorySize, SMEM_BYTES);
    cudaFuncSetAttribute(k_qkv_f,    cudaFuncAttributeMaxDynamicSharedMemorySize, SM_GEMM);
    cudaFuncSetAttribute(k_node_f,   cudaFuncAttributeMaxDynamicSharedMemorySize, SM_NP);
    cudaFuncSetAttribute(k_hout_hp,  cudaFuncAttributeMaxDynamicSharedMemorySize, SM_HOUT);

    k_wT       <<<dim3(8, 8, 2), dim3(32, 32)>>>(Wep, Weg);
    k_node_f   <<<BB*NN/4 + NEH1, 256, SM_NP>>>(node, Wn, bn, E);
    k_qkv_f    <<<3*BB*NN/4 + NEH2, 256, SM_GEMM>>>(Wq, bq, Wk, bk, Wv, bv, E);
    k_scores_f <<<BB*HH*4 + NEH3, 256>>>(E);
    k_edge_attn_mma<<<dim3(HH, BB*NN), 256, SMEM_BYTES>>>(bep, beg, adj);
    k_attn_out <<<BB*128, 256>>>();
    k_hout_hp  <<<BB*NN/4, 256, SM_HOUT>>>(Wo, bo, g1, b1, Weo, out);
    k_edge_out <<<BB*NN*NN/8, 256>>>(E, beo, g2, b2, out);
}

// round 16
// speedup vs baseline: 1.0003x; 1.0003x over previous
#include <cuda_runtime.h>
#include <cuda_fp16.h>
#include <cstdint>
#include <math.h>

#define BB 2
#define NN 256
#define NODE_DIM 128
#define EDGE_DIM 256
#define HID 256
#define HH 8
#define DD 32
#define LN_EPS 1e-5f
#define OUT_EDGE_BASE (BB*NN*HID)

// Eh block distribution across the three prologue kernels
#define NEH1 3000
#define NEH2 3000
#define NEH3 2192

// ---------------- scratch (device globals) ----------------------------------
__device__ __align__(16) float d_h [BB*NN*HID];
__device__ __align__(16) float d_q [BB*NN*HID];
__device__ __align__(16) float d_k [BB*NN*HID];
__device__ __align__(16) float d_v [BB*NN*HID];
__device__ __align__(16) float d_scores[BB*HH*NN*NN];
__device__ __align__(16) float d_am[BB*NN*NN];
__device__ __align__(16) float d_ao[BB*NN*HID];
__device__ __align__(16) float d_hp[BB*NN*HID];
__device__ __align__(16) __half d_Eh  [BB*NN*NN*EDGE_DIM];
__device__ __align__(16) __half d_WpTh[HID*EDGE_DIM];
__device__ __align__(16) __half d_WgTh[HID*EDGE_DIM];

// ---------------- PTX helpers ------------------------------------------------
__device__ __forceinline__ uint32_t smem_u32(const void* p) {
    uint32_t a;
    asm("{ .reg .u64 t; cvta.to.shared.u64 t, %1; cvt.u32.u64 %0, t; }" : "=r"(a) : "l"(p));
    return a;
}
__device__ __forceinline__ void cp_async16(uint32_t dst, const void* src) {
    asm volatile("cp.async.cg.shared.global [%0], [%1], 16;" :: "r"(dst), "l"(src));
}
#define CP_COMMIT() asm volatile("cp.async.commit_group;" ::: "memory")
#define CP_WAIT(n)  asm volatile("cp.async.wait_group %0;" :: "n"(n) : "memory")

__device__ __forceinline__ void mma_f16(float d[4], uint32_t a0, uint32_t a1,
                                        uint32_t a2, uint32_t a3,
                                        uint32_t b0, uint32_t b1) {
    asm volatile(
        "mma.sync.aligned.m16n8k16.row.col.f32.f16.f16.f32 "
        "{%0,%1,%2,%3}, {%4,%5,%6,%7}, {%8,%9}, {%0,%1,%2,%3};"
        : "+f"(d[0]), "+f"(d[1]), "+f"(d[2]), "+f"(d[3])
        : "r"(a0), "r"(a1), "r"(a2), "r"(a3), "r"(b0), "r"(b1));
}
__device__ __forceinline__ uint32_t packh2(float a, float b) {
    __half2 h = __float22half2_rn(make_float2(a, b));
    return *(uint32_t*)&h;
}

// E -> packed fp16 slice (one "block" worth, index eb in [0, 8192))
__device__ __forceinline__ void eh_block(const float* __restrict__ E, int eb) {
    size_t t = (size_t)eb * 256 + threadIdx.x;
    const float4* s = (const float4*)E + t * 4;
    float4 v0 = s[0], v1 = s[1], v2 = s[2], v3 = s[3];
    uint4 o0, o1;
    o0.x = packh2(v0.x, v0.y);
    o0.y = packh2(v2.x, v2.y);
    o0.z = packh2(v0.z, v0.w);
    o0.w = packh2(v2.z, v2.w);
    o1.x = packh2(v1.x, v1.y);
    o1.y = packh2(v3.x, v3.y);
    o1.z = packh2(v1.z, v1.w);
    o1.w = packh2(v3.z, v3.w);
    uint4* d = (uint4*)d_Eh + t * 2;
    d[0] = o0; d[1] = o1;
}

// ---------------- 0a. weight transpose + fp16 pack ---------------------------
__global__ void k_wT(const float* __restrict__ Wep, const float* __restrict__ Weg) {
    __shared__ float t[32][33];
    const float* W = blockIdx.z ? Weg : Wep;
    __half* O = blockIdx.z ? d_WgTh : d_WpTh;
    int n0 = blockIdx.x * 32, k0 = blockIdx.y * 32;
    t[threadIdx.y][threadIdx.x] = W[(k0 + threadIdx.y) * EDGE_DIM + n0 + threadIdx.x];
    __syncthreads();
    float v = t[threadIdx.x][threadIdx.y];
    int k = k0 + threadIdx.x;
    int kk = k & 15;
    int pos = (((kk & 7) >> 1) * 2 + ((kk >> 3) & 1)) * 2 + (kk & 1);
    O[(n0 + threadIdx.y) * EDGE_DIM + (k & ~15) + pos] = __float2half_rn(v);
}

// ---------------- 1. node_proj (+Eh slice) -----------------------------------
#define SM_NP ((NODE_DIM*4 + 2*32*HID)*4)
__global__ void __launch_bounds__(256)
k_node_f(const float* __restrict__ node, const float* __restrict__ Wn,
         const float* __restrict__ bn, const float* __restrict__ E) {
    if (blockIdx.x >= BB*NN/4) { eh_block(E, blockIdx.x - BB*NN/4); return; }
    extern __shared__ float sm[];
    float* st = sm;                    // [128][4] transposed staging
    float* sW = sm + NODE_DIM*4;       // [2][32][256]
    uint32_t wb = smem_u32(sW);
    int tid = threadIdx.x;
    int r0 = blockIdx.x * 4;
    for (int i = tid; i < 4 * NODE_DIM; i += 256) {
        int r = i >> 7, k = i & 127;
        st[k * 4 + r] = node[(r0 + r) * NODE_DIM + k];
    }
    #pragma unroll
    for (int i = 0; i < 8; ++i) {
        int lin = tid + i * 256;
        int row = lin >> 6, c4 = (lin & 63) * 4;
        cp_async16(wb + (row * 256 + c4) * 4, &Wn[row * HID + c4]);
    }
    CP_COMMIT();
    int c = tid;
    float acc[4]; float bb = bn[c];
    #pragma unroll
    for (int r = 0; r < 4; ++r) acc[r] = bb;
    #pragma unroll 1
    for (int t = 0; t < 4; ++t) {
        int buf = t & 1;
        if (t < 3) {
            int nb = buf ^ 1;
            #pragma unroll
            for (int i = 0; i < 8; ++i) {
                int lin = tid + i * 256;
                int row = lin >> 6, c4 = (lin & 63) * 4;
                cp_async16(wb + ((nb * 32 + row) * 256 + c4) * 4,
                           &Wn[((t + 1) * 32 + row) * HID + c4]);
            }
            CP_COMMIT(); CP_WAIT(1);
        } else CP_WAIT(0);
        __syncthreads();
        const float* Wt = sW + buf * 32 * 256;
        #pragma unroll
        for (int k = 0; k < 32; ++k) {
            float w = Wt[k * 256 + c];
            float4 sv = *(const float4*)&st[(t * 32 + k) * 4];
            acc[0] += sv.x * w; acc[1] += sv.y * w;
            acc[2] += sv.z * w; acc[3] += sv.w * w;
        }
        __syncthreads();
    }
    #pragma unroll
    for (int r = 0; r < 4; ++r) d_h[(r0 + r) * HID + c] = acc[r];
}

// ---------------- 2. Q,K,V (+Eh slice) ---------------------------------------
#define SM_GEMM ((HID*4 + 2*32*HID)*4)
__global__ void __launch_bounds__(256)
k_qkv_f(const float* __restrict__ Wq, const float* __restrict__ bq,
        const float* __restrict__ Wk, const float* __restrict__ bk,
        const float* __restrict__ Wv, const float* __restrict__ bv,
        const float* __restrict__ E) {
    if (blockIdx.x >= 3*BB*NN/4) { eh_block(E, NEH1 + blockIdx.x - 3*BB*NN/4); return; }
    extern __shared__ float sm[];
    float* st = sm;                  // [256][4]
    float* sW = sm + HID*4;          // [2][32][256]
    uint32_t wb = smem_u32(sW);
    int z = blockIdx.x / (BB*NN/4);
    int rb = blockIdx.x % (BB*NN/4);
    const float* W  = (z == 0) ? Wq : (z == 1) ? Wk : Wv;
    const float* bi = (z == 0) ? bq : (z == 1) ? bk : bv;
    float* O        = (z == 0) ? d_q : (z == 1) ? d_k : d_v;
    int tid = threadIdx.x;
    int r0 = rb * 4;
    for (int i = tid; i < 4 * HID; i += 256) {
        int r = i >> 8, k = i & 255;
        st[k * 4 + r] = d_h[(r0 + r) * HID + k];
    }
    #pragma unroll
    for (int i = 0; i < 8; ++i) {
        int lin = tid + i * 256;
        int row = lin >> 6, c4 = (lin & 63) * 4;
        cp_async16(wb + (row * 256 + c4) * 4, &W[row * HID + c4]);
    }
    CP_COMMIT();
    int c = tid;
    float acc[4]; float bb = bi[c];
    #pragma unroll
    for (int r = 0; r < 4; ++r) acc[r] = bb;
    #pragma unroll 1
    for (int t = 0; t < 8; ++t) {
        int buf = t & 1;
        if (t < 7) {
            int nb = buf ^ 1;
            #pragma unroll
            for (int i = 0; i < 8; ++i) {
                int lin = tid + i * 256;
                int row = lin >> 6, c4 = (lin & 63) * 4;
                cp_async16(wb + ((nb * 32 + row) * 256 + c4) * 4,
                           &W[((t + 1) * 32 + row) * HID + c4]);
            }
            CP_COMMIT(); CP_WAIT(1);
        } else CP_WAIT(0);
        __syncthreads();
        const float* Wt = sW + buf * 32 * 256;
        #pragma unroll
        for (int k = 0; k < 32; ++k) {
            float w = Wt[k * 256 + c];
            float4 sv = *(const float4*)&st[(t * 32 + k) * 4];
            acc[0] += sv.x * w; acc[1] += sv.y * w;
            acc[2] += sv.z * w; acc[3] += sv.w * w;
        }
        __syncthreads();
    }
    #pragma unroll
    for (int r = 0; r < 4; ++r) O[(r0 + r) * HID + c] = acc[r];
}

// ---------------- 3. scores (+Eh slice) --------------------------------------
#define KS_PAD 36
__global__ void k_scores_f(const float* __restrict__ E) {
    if (blockIdx.x >= BB*HH*4) { eh_block(E, NEH1 + NEH2 + blockIdx.x - BB*HH*4); return; }
    int nt = blockIdx.x & 3;
    int h  = (blockIdx.x >> 2) & 7;
    int b  = blockIdx.x >> 5;
    __shared__ float sQ[64][KS_PAD];
    __shared__ float sK[256][KS_PAD];
    int tid = threadIdx.x;
    #pragma unroll
    for (int i = 0; i < 32; ++i) {
        int idx = tid + i * 256;
        int r = idx >> 5, c = idx & 31;
        sK[r][c] = d_k[(b * NN + r) * HID + h * DD + c];
    }
    #pragma unroll
    for (int i = 0; i < 8; ++i) {
        int idx = tid + i * 256;
        int r = idx >> 5, c = idx & 31;
        sQ[r][c] = d_q[(b * NN + nt * 64 + r) * HID + h * DD + c];
    }
    __syncthreads();
    int nl = tid >> 2, q = tid & 3;
    float qr[32];
    #pragma unroll
    for (int d = 0; d < 32; ++d) qr[d] = sQ[nl][d];
    float* dst = &d_scores[(((size_t)b * HH + h) * NN + nt * 64 + nl) * NN];
    #pragma unroll 4
    for (int i = 0; i < 64; ++i) {
        int m = i * 4 + q;
        float acc = 0.f;
        #pragma unroll
        for (int d = 0; d < 32; ++d) acc += qr[d] * sK[m][d];
        dst[m] = acc * 0.17677669529663687f;
    }
}

// ---------------- 4. edge bias GEMM + fused masked softmax --------------------
#define SA_STRIDE_H 40
#define SA_BUF_H    (256*SA_STRIDE_H)
#define OFF_BP_H    (2*SA_BUF_H)
#define SB_STRIDE_H 264
#define OFF_BG_H    (OFF_BP_H + 32*SB_STRIDE_H)
#define OFF_BIAS_H  (OFF_BG_H + 32*SB_STRIDE_H)
#define SMEM_BYTES  (OFF_BIAS_H*2 + (64+256+256)*4)

__global__ void __launch_bounds__(256, 2)
k_edge_attn_mma(const float* __restrict__ bep, const float* __restrict__ beg,
                const int* __restrict__ adj) {
    extern __shared__ __half smh[];
    const int tid = threadIdx.x;
    const int wid = tid >> 5, lane = tid & 31;
    const int tig = lane & 3, grp = lane >> 2;
    const int h = blockIdx.x;
    const int row0 = blockIdx.y * 256;

    __half* sBp = smh + OFF_BP_H;
    __half* sBg = smh + OFF_BG_H;
    float* sbias = (float*)(smh + OFF_BIAS_H);
    float* sRow  = sbias + 64;
    float* sRed  = sRow + 256;
    uint32_t sA_addr = smem_u32(smh);

    #pragma unroll
    for (int i = 0; i < 4; ++i) {
        int lin = tid + i * 256;
        int n = lin >> 5, q = lin & 31;
        *(uint4*)&sBp[n * SB_STRIDE_H + q * 8] =
            *(const uint4*)&d_WpTh[(h * 32 + n) * EDGE_DIM + q * 8];
        *(uint4*)&sBg[n * SB_STRIDE_H + q * 8] =
            *(const uint4*)&d_WgTh[(h * 32 + n) * EDGE_DIM + q * 8];
    }
    if (tid < 32) {
        sbias[tid]      = bep[h * 32 + tid];
        sbias[32 + tid] = beg[h * 32 + tid];
    }

    float d[2][8][4];
    #pragma unroll
    for (int m = 0; m < 2; ++m)
        #pragma unroll
        for (int j = 0; j < 8; ++j)
            #pragma unroll
            for (int e = 0; e < 4; ++e) d[m][j][e] = 0.f;

    #pragma unroll
    for (int i = 0; i < 4; ++i) {
        int lin = tid + i * 256;
        int r = lin >> 2, q = lin & 3;
        cp_async16(sA_addr + (r * SA_STRIDE_H + q * 8) * 2,
                   &d_Eh[(size_t)(row0 + r) * EDGE_DIM + q * 8]);
    }
    CP_COMMIT();

    #pragma unroll 1
    for (int c = 0; c < 8; ++c) {
        int buf = c & 1;
        if (c < 7) {
            int nb = buf ^ 1;
            #pragma unroll
            for (int i = 0; i < 4; ++i) {
                int lin = tid + i * 256;
                int r = lin >> 2, q = lin & 3;
                cp_async16(sA_addr + (nb * SA_BUF_H + r * SA_STRIDE_H + q * 8) * 2,
                           &d_Eh[(size_t)(row0 + r) * EDGE_DIM + (c + 1) * 32 + q * 8]);
            }
            CP_COMMIT();
            CP_WAIT(1);
        } else {
            CP_WAIT(0);
        }
        __syncthreads();

        const __half* Ab = smh + buf * SA_BUF_H + (wid * 32) * SA_STRIDE_H;
        #pragma unroll
        for (int t = 0; t < 2; ++t) {
            uint2 alo[2], ahi[2];
            #pragma unroll
            for (int m = 0; m < 2; ++m) {
                alo[m] = *(const uint2*)&Ab[(m * 16 + grp) * SA_STRIDE_H + t * 16 + tig * 4];
                ahi[m] = *(const uint2*)&Ab[(m * 16 + grp + 8) * SA_STRIDE_H + t * 16 + tig * 4];
            }
            int kb = c * 32 + t * 16 + tig * 4;
            #pragma unroll
            for (int j = 0; j < 8; ++j) {
                const __half* Bm = (j < 4) ? sBp : sBg;
                uint2 bb = *(const uint2*)&Bm[((j & 3) * 8 + grp) * SB_STRIDE_H + kb];
                mma_f16(d[0][j], alo[0].x, ahi[0].x, alo[0].y, ahi[0].y, bb.x, bb.y);
                mma_f16(d[1][j], alo[1].x, ahi[1].x, alo[1].y, ahi[1].y, bb.x, bb.y);
            }
        }
        __syncthreads();
    }

    #pragma unroll
    for (int m = 0; m < 2; ++m) {
        float s0 = 0.f, s1 = 0.f;
        #pragma unroll
        for (int j = 0; j < 4; ++j) {
            #pragma unroll
            for (int e = 0; e < 2; ++e) {
                int cl = j * 8 + tig * 2 + e;
                float bp = sbias[cl], bg = sbias[32 + cl];
                float p0 = d[m][j][e]     + bp;
                float g0 = d[m][j + 4][e] + bg;
                s0 += p0 / (1.f + expf(-g0));
                float p1 = d[m][j][e + 2]     + bp;
                float g1 = d[m][j + 4][e + 2] + bg;
                s1 += p1 / (1.f + expf(-g1));
            }
        }
        s0 += __shfl_xor_sync(0xffffffffu, s0, 1);
        s0 += __shfl_xor_sync(0xffffffffu, s0, 2);
        s1 += __shfl_xor_sync(0xffffffffu, s1, 1);
        s1 += __shfl_xor_sync(0xffffffffu, s1, 2);
        if (tig == 0) {
            sRow[wid * 32 + m * 16 + grp]     = s0;
            sRow[wid * 32 + m * 16 + grp + 8] = s1;
        }
    }
    __syncthreads();

    {
        int n = blockIdx.y & 255, b = blockIdx.y >> 8;
        size_t base = (((size_t)b * HH + h) * NN + n) * NN;
        float sc = sRow[tid] + d_scores[base + tid];
        if (adj[(b * NN + n) * NN + tid] == 0) sc = -1e9f;
        sRed[tid] = sc; __syncthreads();
        for (int s = 128; s > 0; s >>= 1) {
            if (tid < s) sRed[tid] = fmaxf(sRed[tid], sRed[tid + s]);
            __syncthreads();
        }
        float mx = sRed[0]; __syncthreads();
        float e = expf(sc - mx);
        sRed[tid] = e; __syncthreads();
        for (int s = 128; s > 0; s >>= 1) {
            if (tid < s) sRed[tid] += sRed[tid + s];
            __syncthreads();
        }
        d_scores[base + tid] = e / sRed[0];
    }
}

// ---------------- 6+7. attn_out (2 rows/block) + fused head-mean --------------
__global__ void k_attn_out() {
    int blk = blockIdx.x;                 // 256 blocks: b*128 + nt
    int b = blk >> 7;
    int n0 = (blk & 127) * 2;
    __shared__ float sA[2][HH][NN];       // 16KB
    for (int i = threadIdx.x; i < 2 * HH * NN; i += 256) {
        int r = i >> 11, h = (i >> 8) & 7, m = i & 255;
        sA[r][h][m] = d_scores[(((size_t)b * HH + h) * NN + n0 + r) * NN + m];
    }
    __syncthreads();
    for (int i = threadIdx.x; i < 2 * NN; i += 256) {
        int r = i >> 8, m = i & 255;
        float s = 0.f;
        #pragma unroll
        for (int h2 = 0; h2 < HH; ++h2) s += sA[r][h2][m];
        d_am[(b * NN + n0 + r) * NN + m] = s * (1.f / HH);
    }
    int c = threadIdx.x;
    int h = c >> 5;
    float acc[2] = {0.f, 0.f};
    #pragma unroll 8
    for (int m = 0; m < NN; ++m) {
        float v = d_v[(b * NN + m) * HID + c];
        acc[0] += sA[0][h][m] * v;
        acc[1] += sA[1][h][m] * v;
    }
    d_ao[(b * NN + n0) * HID + c]     = acc[0];
    d_ao[(b * NN + n0 + 1) * HID + c] = acc[1];
}

// ---------------- 8+9. h_out = LN(...) then hp = h_out @ Weo ------------------
#define SM_HOUT ((HID*4 + 2*32*HID + 4*260 + 16)*4)
__global__ void __launch_bounds__(256)
k_hout_hp(const float* __restrict__ Wo, const float* __restrict__ bo,
          const float* __restrict__ g1, const float* __restrict__ b1,
          const float* __restrict__ Weo, float* __restrict__ out) {
    extern __shared__ float sm[];
    float* st  = sm;                       // [256][4] transposed staging
    float* sW  = sm + HID*4;               // [2][32][256]
    float* sy  = sW + 2*32*HID;            // [4][260]
    float* prt = sy + 4*260;               // [16]
    uint32_t wb = smem_u32(sW);
    int tid = threadIdx.x;
    int wid = tid >> 5, lane = tid & 31;
    int r0 = blockIdx.x * 4;
    for (int i = tid; i < 4 * HID; i += 256) {
        int r = i >> 8, k = i & 255;
        st[k * 4 + r] = d_ao[(r0 + r) * HID + k];
    }
    #pragma unroll
    for (int i = 0; i < 8; ++i) {
        int lin = tid + i * 256;
        int row = lin >> 6, c4 = (lin & 63) * 4;
        cp_async16(wb + (row * 256 + c4) * 4, &Wo[row * HID + c4]);
    }
    CP_COMMIT();
    int c = tid;
    float acc[4]; float bb = bo[c];
    #pragma unroll
    for (int r = 0; r < 4; ++r) acc[r] = bb;
    #pragma unroll 1
    for (int t = 0; t < 8; ++t) {
        int buf = t & 1;
        if (t < 7) {
            int nb = buf ^ 1;
            #pragma unroll
            for (int i = 0; i < 8; ++i) {
                int lin = tid + i * 256;
                int row = lin >> 6, c4 = (lin & 63) * 4;
                cp_async16(wb + ((nb * 32 + row) * 256 + c4) * 4,
                           &Wo[((t + 1) * 32 + row) * HID + c4]);
            }
            CP_COMMIT(); CP_WAIT(1);
        } else CP_WAIT(0);
        __syncthreads();
        const float* Wt = sW + buf * 32 * 256;
        #pragma unroll
        for (int k = 0; k < 32; ++k) {
            float w = Wt[k * 256 + c];
            float4 sv = *(const float4*)&st[(t * 32 + k) * 4];
            acc[0] += sv.x * w; acc[1] += sv.y * w;
            acc[2] += sv.z * w; acc[3] += sv.w * w;
        }
        __syncthreads();
    }
    #pragma unroll
    for (int r = 0; r < 4; ++r)
        sy[r * 260 + c] = acc[r] + d_h[(r0 + r) * HID + c];
    __syncthreads();
    {
        int rw = wid >> 1, off = (wid & 1) * 128;
        float ps = 0.f, ps2 = 0.f;
        #pragma unroll
        for (int j = 0; j < 4; ++j) {
            float v = sy[rw * 260 + off + j * 32 + lane];
            ps += v; ps2 += v * v;
        }
        #pragma unroll
        for (int o = 16; o > 0; o >>= 1) {
            ps  += __shfl_xor_sync(0xffffffffu, ps,  o);
            ps2 += __shfl_xor_sync(0xffffffffu, ps2, o);
        }
        if (lane == 0) { prt[wid] = ps; prt[8 + wid] = ps2; }
    }
    __syncthreads();
    float gg = g1[c], bb1 = b1[c];
    #pragma unroll
    for (int r = 0; r < 4; ++r) {
        float sum  = prt[r * 2] + prt[r * 2 + 1];
        float sum2 = prt[8 + r * 2] + prt[8 + r * 2 + 1];
        float mean = sum * (1.f / HID);
        float var  = sum2 * (1.f / HID) - mean * mean;
        float y = sy[r * 260 + c];
        float o = (y - mean) * rsqrtf(var + LN_EPS) * gg + bb1;
        out[(r0 + r) * HID + c] = o;
        st[c * 4 + r] = o;                // re-stage transposed for phase 2
    }
    __syncthreads();

    // ---- phase 2: hp = h_out @ Weo ----
    #pragma unroll
    for (int i = 0; i < 8; ++i) {
        int lin = tid + i * 256;
        int row = lin >> 6, c4 = (lin & 63) * 4;
        cp_async16(wb + (row * 256 + c4) * 4, &Weo[row * EDGE_DIM + c4]);
    }
    CP_COMMIT();
    float acc2[4] = {0.f, 0.f, 0.f, 0.f};
    #pragma unroll 1
    for (int t = 0; t < 8; ++t) {
        int buf = t & 1;
        if (t < 7) {
            int nb = buf ^ 1;
            #pragma unroll
            for (int i = 0; i < 8; ++i) {
                int lin = tid + i * 256;
                int row = lin >> 6, c4 = (lin & 63) * 4;
                cp_async16(wb + ((nb * 32 + row) * 256 + c4) * 4,
                           &Weo[((t + 1) * 32 + row) * EDGE_DIM + c4]);
            }
            CP_COMMIT(); CP_WAIT(1);
        } else CP_WAIT(0);
        __syncthreads();
        const float* Wt = sW + buf * 32 * 256;
        #pragma unroll
        for (int k = 0; k < 32; ++k) {
            float w = Wt[k * 256 + c];
            float4 sv = *(const float4*)&st[(t * 32 + k) * 4];
            acc2[0] += sv.x * w; acc2[1] += sv.y * w;
            acc2[2] += sv.z * w; acc2[3] += sv.w * w;
        }
        __syncthreads();
    }
    #pragma unroll
    for (int r = 0; r < 4; ++r) d_hp[(r0 + r) * EDGE_DIM + c] = acc2[r];
}

// ---------------- 10. edge_out (float4) ---------------------------------------
__global__ void k_edge_out(const float* __restrict__ E,
                           const float* __restrict__ beo,
                           const float* __restrict__ g2,
                           const float* __restrict__ b2,
                           float* __restrict__ out) {
    int w = blockIdx.x * 8 + (threadIdx.x >> 5);
    int lane = threadIdx.x & 31;
    int m = w & 255, n = (w >> 8) & 255, b = w >> 16;
    float am = d_am[w] * 0.5f;
    const float4* Er = (const float4*)&E[(size_t)w * EDGE_DIM];
    const float4* hn = (const float4*)&d_hp[(b * NN + n) * EDGE_DIM];
    const float4* hm = (const float4*)&d_hp[(b * NN + m) * EDGE_DIM];
    const float4* bo4 = (const float4*)beo;
    float4 x[2];
    float s = 0.f, s2 = 0.f;
    #pragma unroll
    for (int j = 0; j < 2; ++j) {
        int idx = j * 32 + lane;
        float4 e = Er[idx], a = hn[idx], cc = hm[idx], bb = bo4[idx];
        float4 v;
        v.x = e.x + am * (a.x + cc.x) + bb.x;
        v.y = e.y + am * (a.y + cc.y) + bb.y;
        v.z = e.z + am * (a.z + cc.z) + bb.z;
        v.w = e.w + am * (a.w + cc.w) + bb.w;
        x[j] = v;
        s  += v.x + v.y + v.z + v.w;
        s2 += v.x*v.x + v.y*v.y + v.z*v.z + v.w*v.w;
    }
    #pragma unroll
    for (int o = 16; o > 0; o >>= 1) {
        s  += __shfl_xor_sync(0xffffffffu, s,  o);
        s2 += __shfl_xor_sync(0xffffffffu, s2, o);
    }
    float mean = s * (1.f / EDGE_DIM);
    float var  = s2 * (1.f / EDGE_DIM) - mean * mean;
    float rinv = rsqrtf(var + LN_EPS);
    const float4* g4 = (const float4*)g2;
    const float4* b4 = (const float4*)b2;
    float4* op = (float4*)&out[OUT_EDGE_BASE + (size_t)w * EDGE_DIM];
    #pragma unroll
    for (int j = 0; j < 2; ++j) {
        int idx = j * 32 + lane;
        float4 g = g4[idx], bb = b4[idx], v = x[j], o4;
        o4.x = (v.x - mean) * rinv * g.x + bb.x;
        o4.y = (v.y - mean) * rinv * g.y + bb.y;
        o4.z = (v.z - mean) * rinv * g.z + bb.z;
        o4.w = (v.w - mean) * rinv * g.w + bb.w;
        op[idx] = o4;
    }
}

// ---------------- launch ------------------------------------------------------
extern "C" void kernel_launch(void* const* d_in, const int* in_sizes, int n_in,
                              void* d_out, int out_size) {
    const float* node = (const float*)d_in[0];
    const float* E    = (const float*)d_in[1];
    const int*   adj  = (const int*)  d_in[2];
    const float* Wn  = (const float*)d_in[3];  const float* bn  = (const float*)d_in[4];
    const float* Wq  = (const float*)d_in[5];  const float* bq  = (const float*)d_in[6];
    const float* Wk  = (const float*)d_in[7];  const float* bk  = (const float*)d_in[8];
    const float* Wv  = (const float*)d_in[9];  const float* bv  = (const float*)d_in[10];
    const float* Wep = (const float*)d_in[11]; const float* bep = (const float*)d_in[12];
    const float* Weg = (const float*)d_in[13]; const float* beg = (const float*)d_in[14];
    const float* Wo  = (const float*)d_in[15]; const float* bo  = (const float*)d_in[16];
    const float* Weo = (const float*)d_in[17]; const float* beo = (const float*)d_in[18];
    const float* g1  = (const float*)d_in[19]; const float* b1  = (const float*)d_in[20];
    const float* g2  = (const float*)d_in[21]; const float* b2  = (const float*)d_in[22];
    float* out = (float*)d_out;

    cudaFuncSetAttribute(k_edge_attn_mma, cudaFuncAttributeMaxDynamicSharedMemorySize, SMEM_BYTES);
    cudaFuncSetAttribute(k_qkv_f,    cudaFuncAttributeMaxDynamicSharedMemorySize, SM_GEMM);
    cudaFuncSetAttribute(k_node_f,   cudaFuncAttributeMaxDynamicSharedMemorySize, SM_NP);
    cudaFuncSetAttribute(k_hout_hp,  cudaFuncAttributeMaxDynamicSharedMemorySize, SM_HOUT);

    k_wT       <<<dim3(8, 8, 2), dim3(32, 32)>>>(Wep, Weg);
    k_node_f   <<<BB*NN/4 + NEH1, 256, SM_NP>>>(node, Wn, bn, E);
    k_qkv_f    <<<3*BB*NN/4 + NEH2, 256, SM_GEMM>>>(Wq, bq, Wk, bk, Wv, bv, E);
    k_scores_f <<<BB*HH*4 + NEH3, 256>>>(E);
    k_edge_attn_mma<<<dim3(HH, BB*NN), 256, SMEM_BYTES>>>(bep, beg, adj);
    k_attn_out <<<BB*128, 256>>>();
    k_hout_hp  <<<BB*NN/4, 256, SM_HOUT>>>(Wo, bo, g1, b1, Weo, out);
    k_edge_out <<<BB*NN*NN/8, 256>>>(E, beo, g2, b2, out);
}

// round 17
// speedup vs baseline: 1.0028x; 1.0025x over previous
#include <cuda_runtime.h>
#include <cuda_fp16.h>
#include <cstdint>
#include <math.h>

#define BB 2
#define NN 256
#define NODE_DIM 128
#define EDGE_DIM 256
#define HID 256
#define HH 8
#define DD 32
#define LN_EPS 1e-5f
#define OUT_EDGE_BASE (BB*NN*HID)

// Eh block distribution across the three prologue kernels
#define NEH1 3000
#define NEH2 3000
#define NEH3 2192

// ---------------- scratch (device globals) ----------------------------------
__device__ __align__(16) float d_h [BB*NN*HID];
__device__ __align__(16) float d_q [BB*NN*HID];
__device__ __align__(16) float d_k [BB*NN*HID];
__device__ __align__(16) float d_v [BB*NN*HID];
__device__ __align__(16) float d_scores[BB*HH*NN*NN];
__device__ __align__(16) float d_am[BB*NN*NN];
__device__ __align__(16) float d_ao[BB*NN*HID];
__device__ __align__(16) float d_hp[BB*NN*HID];
__device__ __align__(16) __half d_Eh  [BB*NN*NN*EDGE_DIM];
__device__ __align__(16) __half d_WpTh[HID*EDGE_DIM];
__device__ __align__(16) __half d_WgTh[HID*EDGE_DIM];

// ---------------- PTX helpers ------------------------------------------------
__device__ __forceinline__ uint32_t smem_u32(const void* p) {
    uint32_t a;
    asm("{ .reg .u64 t; cvta.to.shared.u64 t, %1; cvt.u32.u64 %0, t; }" : "=r"(a) : "l"(p));
    return a;
}
__device__ __forceinline__ void cp_async16(uint32_t dst, const void* src) {
    asm volatile("cp.async.cg.shared.global [%0], [%1], 16;" :: "r"(dst), "l"(src));
}
#define CP_COMMIT() asm volatile("cp.async.commit_group;" ::: "memory")
#define CP_WAIT(n)  asm volatile("cp.async.wait_group %0;" :: "n"(n) : "memory")

__device__ __forceinline__ void mma_f16(float d[4], uint32_t a0, uint32_t a1,
                                        uint32_t a2, uint32_t a3,
                                        uint32_t b0, uint32_t b1) {
    asm volatile(
        "mma.sync.aligned.m16n8k16.row.col.f32.f16.f16.f32 "
        "{%0,%1,%2,%3}, {%4,%5,%6,%7}, {%8,%9}, {%0,%1,%2,%3};"
        : "+f"(d[0]), "+f"(d[1]), "+f"(d[2]), "+f"(d[3])
        : "r"(a0), "r"(a1), "r"(a2), "r"(a3), "r"(b0), "r"(b1));
}
__device__ __forceinline__ uint32_t packh2(float a, float b) {
    __half2 h = __float22half2_rn(make_float2(a, b));
    return *(uint32_t*)&h;
}

// E -> packed fp16 slice (one "block" worth, index eb in [0, 8192))
__device__ __forceinline__ void eh_block(const float* __restrict__ E, int eb) {
    size_t t = (size_t)eb * 256 + threadIdx.x;
    const float4* s = (const float4*)E + t * 4;
    float4 v0 = s[0], v1 = s[1], v2 = s[2], v3 = s[3];
    uint4 o0, o1;
    o0.x = packh2(v0.x, v0.y);
    o0.y = packh2(v2.x, v2.y);
    o0.z = packh2(v0.z, v0.w);
    o0.w = packh2(v2.z, v2.w);
    o1.x = packh2(v1.x, v1.y);
    o1.y = packh2(v3.x, v3.y);
    o1.z = packh2(v1.z, v1.w);
    o1.w = packh2(v3.z, v3.w);
    uint4* d = (uint4*)d_Eh + t * 2;
    d[0] = o0; d[1] = o1;
}

// ---------------- 0a. weight transpose + fp16 pack ---------------------------
__global__ void k_wT(const float* __restrict__ Wep, const float* __restrict__ Weg) {
    __shared__ float t[32][33];
    const float* W = blockIdx.z ? Weg : Wep;
    __half* O = blockIdx.z ? d_WgTh : d_WpTh;
    int n0 = blockIdx.x * 32, k0 = blockIdx.y * 32;
    t[threadIdx.y][threadIdx.x] = W[(k0 + threadIdx.y) * EDGE_DIM + n0 + threadIdx.x];
    __syncthreads();
    float v = t[threadIdx.x][threadIdx.y];
    int k = k0 + threadIdx.x;
    int kk = k & 15;
    int pos = (((kk & 7) >> 1) * 2 + ((kk >> 3) & 1)) * 2 + (kk & 1);
    O[(n0 + threadIdx.y) * EDGE_DIM + (k & ~15) + pos] = __float2half_rn(v);
}

// ---------------- 1. node_proj (+Eh slice) -----------------------------------
#define SM_NP ((NODE_DIM*4 + 2*32*HID)*4)
__global__ void __launch_bounds__(256)
k_node_f(const float* __restrict__ node, const float* __restrict__ Wn,
         const float* __restrict__ bn, const float* __restrict__ E) {
    if (blockIdx.x >= BB*NN/4) { eh_block(E, blockIdx.x - BB*NN/4); return; }
    extern __shared__ float sm[];
    float* st = sm;                    // [128][4] transposed staging
    float* sW = sm + NODE_DIM*4;       // [2][32][256]
    uint32_t wb = smem_u32(sW);
    int tid = threadIdx.x;
    int r0 = blockIdx.x * 4;
    for (int i = tid; i < 4 * NODE_DIM; i += 256) {
        int r = i >> 7, k = i & 127;
        st[k * 4 + r] = node[(r0 + r) * NODE_DIM + k];
    }
    #pragma unroll
    for (int i = 0; i < 8; ++i) {
        int lin = tid + i * 256;
        int row = lin >> 6, c4 = (lin & 63) * 4;
        cp_async16(wb + (row * 256 + c4) * 4, &Wn[row * HID + c4]);
    }
    CP_COMMIT();
    int c = tid;
    float acc[4]; float bb = bn[c];
    #pragma unroll
    for (int r = 0; r < 4; ++r) acc[r] = bb;
    #pragma unroll 1
    for (int t = 0; t < 4; ++t) {
        int buf = t & 1;
        if (t < 3) {
            int nb = buf ^ 1;
            #pragma unroll
            for (int i = 0; i < 8; ++i) {
                int lin = tid + i * 256;
                int row = lin >> 6, c4 = (lin & 63) * 4;
                cp_async16(wb + ((nb * 32 + row) * 256 + c4) * 4,
                           &Wn[((t + 1) * 32 + row) * HID + c4]);
            }
            CP_COMMIT(); CP_WAIT(1);
        } else CP_WAIT(0);
        __syncthreads();
        const float* Wt = sW + buf * 32 * 256;
        #pragma unroll
        for (int k = 0; k < 32; ++k) {
            float w = Wt[k * 256 + c];
            float4 sv = *(const float4*)&st[(t * 32 + k) * 4];
            acc[0] += sv.x * w; acc[1] += sv.y * w;
            acc[2] += sv.z * w; acc[3] += sv.w * w;
        }
        __syncthreads();
    }
    #pragma unroll
    for (int r = 0; r < 4; ++r) d_h[(r0 + r) * HID + c] = acc[r];
}

// ---------------- 2. Q,K,V (+Eh slice) ---------------------------------------
#define SM_GEMM ((HID*4 + 2*32*HID)*4)
__global__ void __launch_bounds__(256)
k_qkv_f(const float* __restrict__ Wq, const float* __restrict__ bq,
        const float* __restrict__ Wk, const float* __restrict__ bk,
        const float* __restrict__ Wv, const float* __restrict__ bv,
        const float* __restrict__ E) {
    if (blockIdx.x >= 3*BB*NN/4) { eh_block(E, NEH1 + blockIdx.x - 3*BB*NN/4); return; }
    extern __shared__ float sm[];
    float* st = sm;                  // [256][4]
    float* sW = sm + HID*4;          // [2][32][256]
    uint32_t wb = smem_u32(sW);
    int z = blockIdx.x / (BB*NN/4);
    int rb = blockIdx.x % (BB*NN/4);
    const float* W  = (z == 0) ? Wq : (z == 1) ? Wk : Wv;
    const float* bi = (z == 0) ? bq : (z == 1) ? bk : bv;
    float* O        = (z == 0) ? d_q : (z == 1) ? d_k : d_v;
    int tid = threadIdx.x;
    int r0 = rb * 4;
    for (int i = tid; i < 4 * HID; i += 256) {
        int r = i >> 8, k = i & 255;
        st[k * 4 + r] = d_h[(r0 + r) * HID + k];
    }
    #pragma unroll
    for (int i = 0; i < 8; ++i) {
        int lin = tid + i * 256;
        int row = lin >> 6, c4 = (lin & 63) * 4;
        cp_async16(wb + (row * 256 + c4) * 4, &W[row * HID + c4]);
    }
    CP_COMMIT();
    int c = tid;
    float acc[4]; float bb = bi[c];
    #pragma unroll
    for (int r = 0; r < 4; ++r) acc[r] = bb;
    #pragma unroll 1
    for (int t = 0; t < 8; ++t) {
        int buf = t & 1;
        if (t < 7) {
            int nb = buf ^ 1;
            #pragma unroll
            for (int i = 0; i < 8; ++i) {
                int lin = tid + i * 256;
                int row = lin >> 6, c4 = (lin & 63) * 4;
                cp_async16(wb + ((nb * 32 + row) * 256 + c4) * 4,
                           &W[((t + 1) * 32 + row) * HID + c4]);
            }
            CP_COMMIT(); CP_WAIT(1);
        } else CP_WAIT(0);
        __syncthreads();
        const float* Wt = sW + buf * 32 * 256;
        #pragma unroll
        for (int k = 0; k < 32; ++k) {
            float w = Wt[k * 256 + c];
            float4 sv = *(const float4*)&st[(t * 32 + k) * 4];
            acc[0] += sv.x * w; acc[1] += sv.y * w;
            acc[2] += sv.z * w; acc[3] += sv.w * w;
        }
        __syncthreads();
    }
    #pragma unroll
    for (int r = 0; r < 4; ++r) O[(r0 + r) * HID + c] = acc[r];
}

// ---------------- 3. scores (+Eh slice) --------------------------------------
#define KS_PAD 36
__global__ void k_scores_f(const float* __restrict__ E) {
    if (blockIdx.x >= BB*HH*4) { eh_block(E, NEH1 + NEH2 + blockIdx.x - BB*HH*4); return; }
    int nt = blockIdx.x & 3;
    int h  = (blockIdx.x >> 2) & 7;
    int b  = blockIdx.x >> 5;
    __shared__ float sQ[64][KS_PAD];
    __shared__ float sK[256][KS_PAD];
    int tid = threadIdx.x;
    #pragma unroll
    for (int i = 0; i < 32; ++i) {
        int idx = tid + i * 256;
        int r = idx >> 5, c = idx & 31;
        sK[r][c] = d_k[(b * NN + r) * HID + h * DD + c];
    }
    #pragma unroll
    for (int i = 0; i < 8; ++i) {
        int idx = tid + i * 256;
        int r = idx >> 5, c = idx & 31;
        sQ[r][c] = d_q[(b * NN + nt * 64 + r) * HID + h * DD + c];
    }
    __syncthreads();
    int nl = tid >> 2, q = tid & 3;
    float qr[32];
    #pragma unroll
    for (int d = 0; d < 32; ++d) qr[d] = sQ[nl][d];
    float* dst = &d_scores[(((size_t)b * HH + h) * NN + nt * 64 + nl) * NN];
    #pragma unroll 4
    for (int i = 0; i < 64; ++i) {
        int m = i * 4 + q;
        float acc = 0.f;
        #pragma unroll
        for (int d = 0; d < 32; ++d) acc += qr[d] * sK[m][d];
        dst[m] = acc * 0.17677669529663687f;
    }
}

// ---------------- 4. edge bias GEMM + fused masked softmax --------------------
#define SA_STRIDE_H 40
#define SA_BUF_H    (256*SA_STRIDE_H)
#define OFF_BP_H    (2*SA_BUF_H)
#define SB_STRIDE_H 264
#define OFF_BG_H    (OFF_BP_H + 32*SB_STRIDE_H)
#define OFF_BIAS_H  (OFF_BG_H + 32*SB_STRIDE_H)
#define SMEM_BYTES  (OFF_BIAS_H*2 + (64+256+256)*4)

__global__ void __launch_bounds__(256, 2)
k_edge_attn_mma(const float* __restrict__ bep, const float* __restrict__ beg,
                const int* __restrict__ adj) {
    extern __shared__ __half smh[];
    const int tid = threadIdx.x;
    const int wid = tid >> 5, lane = tid & 31;
    const int tig = lane & 3, grp = lane >> 2;
    const int h = blockIdx.x;
    const int row0 = blockIdx.y * 256;

    __half* sBp = smh + OFF_BP_H;
    __half* sBg = smh + OFF_BG_H;
    float* sbias = (float*)(smh + OFF_BIAS_H);
    float* sRow  = sbias + 64;
    float* sRed  = sRow + 256;
    uint32_t sA_addr = smem_u32(smh);

    #pragma unroll
    for (int i = 0; i < 4; ++i) {
        int lin = tid + i * 256;
        int n = lin >> 5, q = lin & 31;
        *(uint4*)&sBp[n * SB_STRIDE_H + q * 8] =
            *(const uint4*)&d_WpTh[(h * 32 + n) * EDGE_DIM + q * 8];
        *(uint4*)&sBg[n * SB_STRIDE_H + q * 8] =
            *(const uint4*)&d_WgTh[(h * 32 + n) * EDGE_DIM + q * 8];
    }
    if (tid < 32) {
        sbias[tid]      = bep[h * 32 + tid];
        sbias[32 + tid] = beg[h * 32 + tid];
    }

    float d[2][8][4];
    #pragma unroll
    for (int m = 0; m < 2; ++m)
        #pragma unroll
        for (int j = 0; j < 8; ++j)
            #pragma unroll
            for (int e = 0; e < 4; ++e) d[m][j][e] = 0.f;

    #pragma unroll
    for (int i = 0; i < 4; ++i) {
        int lin = tid + i * 256;
        int r = lin >> 2, q = lin & 3;
        cp_async16(sA_addr + (r * SA_STRIDE_H + q * 8) * 2,
                   &d_Eh[(size_t)(row0 + r) * EDGE_DIM + q * 8]);
    }
    CP_COMMIT();

    #pragma unroll 1
    for (int c = 0; c < 8; ++c) {
        int buf = c & 1;
        if (c < 7) {
            int nb = buf ^ 1;
            #pragma unroll
            for (int i = 0; i < 4; ++i) {
                int lin = tid + i * 256;
                int r = lin >> 2, q = lin & 3;
                cp_async16(sA_addr + (nb * SA_BUF_H + r * SA_STRIDE_H + q * 8) * 2,
                           &d_Eh[(size_t)(row0 + r) * EDGE_DIM + (c + 1) * 32 + q * 8]);
            }
            CP_COMMIT();
            CP_WAIT(1);
        } else {
            CP_WAIT(0);
        }
        __syncthreads();

        const __half* Ab = smh + buf * SA_BUF_H + (wid * 32) * SA_STRIDE_H;
        #pragma unroll
        for (int t = 0; t < 2; ++t) {
            uint2 alo[2], ahi[2];
            #pragma unroll
            for (int m = 0; m < 2; ++m) {
                alo[m] = *(const uint2*)&Ab[(m * 16 + grp) * SA_STRIDE_H + t * 16 + tig * 4];
                ahi[m] = *(const uint2*)&Ab[(m * 16 + grp + 8) * SA_STRIDE_H + t * 16 + tig * 4];
            }
            int kb = c * 32 + t * 16 + tig * 4;
            #pragma unroll
            for (int j = 0; j < 8; ++j) {
                const __half* Bm = (j < 4) ? sBp : sBg;
                uint2 bb = *(const uint2*)&Bm[((j & 3) * 8 + grp) * SB_STRIDE_H + kb];
                mma_f16(d[0][j], alo[0].x, ahi[0].x, alo[0].y, ahi[0].y, bb.x, bb.y);
                mma_f16(d[1][j], alo[1].x, ahi[1].x, alo[1].y, ahi[1].y, bb.x, bb.y);
            }
        }
        __syncthreads();
    }

    #pragma unroll
    for (int m = 0; m < 2; ++m) {
        float s0 = 0.f, s1 = 0.f;
        #pragma unroll
        for (int j = 0; j < 4; ++j) {
            #pragma unroll
            for (int e = 0; e < 2; ++e) {
                int cl = j * 8 + tig * 2 + e;
                float bp = sbias[cl], bg = sbias[32 + cl];
                float p0 = d[m][j][e]     + bp;
                float g0 = d[m][j + 4][e] + bg;
                s0 += p0 / (1.f + expf(-g0));
                float p1 = d[m][j][e + 2]     + bp;
                float g1 = d[m][j + 4][e + 2] + bg;
                s1 += p1 / (1.f + expf(-g1));
            }
        }
        s0 += __shfl_xor_sync(0xffffffffu, s0, 1);
        s0 += __shfl_xor_sync(0xffffffffu, s0, 2);
        s1 += __shfl_xor_sync(0xffffffffu, s1, 1);
        s1 += __shfl_xor_sync(0xffffffffu, s1, 2);
        if (tig == 0) {
            sRow[wid * 32 + m * 16 + grp]     = s0;
            sRow[wid * 32 + m * 16 + grp + 8] = s1;
        }
    }
    __syncthreads();

    {
        int n = blockIdx.y & 255, b = blockIdx.y >> 8;
        size_t base = (((size_t)b * HH + h) * NN + n) * NN;
        float sc = sRow[tid] + d_scores[base + tid];
        if (adj[(b * NN + n) * NN + tid] == 0) sc = -1e9f;
        sRed[tid] = sc; __syncthreads();
        for (int s = 128; s > 0; s >>= 1) {
            if (tid < s) sRed[tid] = fmaxf(sRed[tid], sRed[tid + s]);
            __syncthreads();
        }
        float mx = sRed[0]; __syncthreads();
        float e = expf(sc - mx);
        sRed[tid] = e; __syncthreads();
        for (int s = 128; s > 0; s >>= 1) {
            if (tid < s) sRed[tid] += sRed[tid + s];
            __syncthreads();
        }
        d_scores[base + tid] = e / sRed[0];
    }
}

// ---------------- 6+7. attn_out (2 rows/block) + fused head-mean --------------
__global__ void k_attn_out() {
    int blk = blockIdx.x;                 // 256 blocks: b*128 + nt
    int b = blk >> 7;
    int n0 = (blk & 127) * 2;
    __shared__ float sA[2][HH][NN];       // 16KB
    for (int i = threadIdx.x; i < 2 * HH * NN; i += 256) {
        int r = i >> 11, h = (i >> 8) & 7, m = i & 255;
        sA[r][h][m] = d_scores[(((size_t)b * HH + h) * NN + n0 + r) * NN + m];
    }
    __syncthreads();
    for (int i = threadIdx.x; i < 2 * NN; i += 256) {
        int r = i >> 8, m = i & 255;
        float s = 0.f;
        #pragma unroll
        for (int h2 = 0; h2 < HH; ++h2) s += sA[r][h2][m];
        d_am[(b * NN + n0 + r) * NN + m] = s * (1.f / HH);
    }
    int c = threadIdx.x;
    int h = c >> 5;
    float acc[2] = {0.f, 0.f};
    #pragma unroll 8
    for (int m = 0; m < NN; ++m) {
        float v = d_v[(b * NN + m) * HID + c];
        acc[0] += sA[0][h][m] * v;
        acc[1] += sA[1][h][m] * v;
    }
    d_ao[(b * NN + n0) * HID + c]     = acc[0];
    d_ao[(b * NN + n0 + 1) * HID + c] = acc[1];
}

// ---------------- 8+9. h_out = LN(...) then hp = h_out @ Weo ------------------
#define SM_HOUT ((HID*4 + 2*32*HID + 4*260 + 16)*4)
__global__ void __launch_bounds__(256)
k_hout_hp(const float* __restrict__ Wo, const float* __restrict__ bo,
          const float* __restrict__ g1, const float* __restrict__ b1,
          const float* __restrict__ Weo, float* __restrict__ out) {
    extern __shared__ float sm[];
    float* st  = sm;                       // [256][4] transposed staging
    float* sW  = sm + HID*4;               // [2][32][256]
    float* sy  = sW + 2*32*HID;            // [4][260]
    float* prt = sy + 4*260;               // [16]
    uint32_t wb = smem_u32(sW);
    int tid = threadIdx.x;
    int wid = tid >> 5, lane = tid & 31;
    int r0 = blockIdx.x * 4;
    for (int i = tid; i < 4 * HID; i += 256) {
        int r = i >> 8, k = i & 255;
        st[k * 4 + r] = d_ao[(r0 + r) * HID + k];
    }
    #pragma unroll
    for (int i = 0; i < 8; ++i) {
        int lin = tid + i * 256;
        int row = lin >> 6, c4 = (lin & 63) * 4;
        cp_async16(wb + (row * 256 + c4) * 4, &Wo[row * HID + c4]);
    }
    CP_COMMIT();
    int c = tid;
    float acc[4]; float bb = bo[c];
    #pragma unroll
    for (int r = 0; r < 4; ++r) acc[r] = bb;
    #pragma unroll 1
    for (int t = 0; t < 8; ++t) {
        int buf = t & 1;
        if (t < 7) {
            int nb = buf ^ 1;
            #pragma unroll
            for (int i = 0; i < 8; ++i) {
                int lin = tid + i * 256;
                int row = lin >> 6, c4 = (lin & 63) * 4;
                cp_async16(wb + ((nb * 32 + row) * 256 + c4) * 4,
                           &Wo[((t + 1) * 32 + row) * HID + c4]);
            }
            CP_COMMIT(); CP_WAIT(1);
        } else CP_WAIT(0);
        __syncthreads();
        const float* Wt = sW + buf * 32 * 256;
        #pragma unroll
        for (int k = 0; k < 32; ++k) {
            float w = Wt[k * 256 + c];
            float4 sv = *(const float4*)&st[(t * 32 + k) * 4];
            acc[0] += sv.x * w; acc[1] += sv.y * w;
            acc[2] += sv.z * w; acc[3] += sv.w * w;
        }
        __syncthreads();
    }
    #pragma unroll
    for (int r = 0; r < 4; ++r)
        sy[r * 260 + c] = acc[r] + d_h[(r0 + r) * HID + c];
    __syncthreads();
    {
        int rw = wid >> 1, off = (wid & 1) * 128;
        float ps = 0.f, ps2 = 0.f;
        #pragma unroll
        for (int j = 0; j < 4; ++j) {
            float v = sy[rw * 260 + off + j * 32 + lane];
            ps += v; ps2 += v * v;
        }
        #pragma unroll
        for (int o = 16; o > 0; o >>= 1) {
            ps  += __shfl_xor_sync(0xffffffffu, ps,  o);
            ps2 += __shfl_xor_sync(0xffffffffu, ps2, o);
        }
        if (lane == 0) { prt[wid] = ps; prt[8 + wid] = ps2; }
    }
    __syncthreads();
    float gg = g1[c], bb1 = b1[c];
    #pragma unroll
    for (int r = 0; r < 4; ++r) {
        float sum  = prt[r * 2] + prt[r * 2 + 1];
        float sum2 = prt[8 + r * 2] + prt[8 + r * 2 + 1];
        float mean = sum * (1.f / HID);
        float var  = sum2 * (1.f / HID) - mean * mean;
        float y = sy[r * 260 + c];
        float o = (y - mean) * rsqrtf(var + LN_EPS) * gg + bb1;
        out[(r0 + r) * HID + c] = o;
        st[c * 4 + r] = o;                // re-stage transposed for phase 2
    }
    __syncthreads();

    // ---- phase 2: hp = h_out @ Weo ----
    #pragma unroll
    for (int i = 0; i < 8; ++i) {
        int lin = tid + i * 256;
        int row = lin >> 6, c4 = (lin & 63) * 4;
        cp_async16(wb + (row * 256 + c4) * 4, &Weo[row * EDGE_DIM + c4]);
    }
    CP_COMMIT();
    float acc2[4] = {0.f, 0.f, 0.f, 0.f};
    #pragma unroll 1
    for (int t = 0; t < 8; ++t) {
        int buf = t & 1;
        if (t < 7) {
            int nb = buf ^ 1;
            #pragma unroll
            for (int i = 0; i < 8; ++i) {
                int lin = tid + i * 256;
                int row = lin >> 6, c4 = (lin & 63) * 4;
                cp_async16(wb + ((nb * 32 + row) * 256 + c4) * 4,
                           &Weo[((t + 1) * 32 + row) * EDGE_DIM + c4]);
            }
            CP_COMMIT(); CP_WAIT(1);
        } else CP_WAIT(0);
        __syncthreads();
        const float* Wt = sW + buf * 32 * 256;
        #pragma unroll
        for (int k = 0; k < 32; ++k) {
            float w = Wt[k * 256 + c];
            float4 sv = *(const float4*)&st[(t * 32 + k) * 4];
            acc2[0] += sv.x * w; acc2[1] += sv.y * w;
            acc2[2] += sv.z * w; acc2[3] += sv.w * w;
        }
        __syncthreads();
    }
    #pragma unroll
    for (int r = 0; r < 4; ++r) d_hp[(r0 + r) * EDGE_DIM + c] = acc2[r];
}

// ---------------- 10. edge_out (float4) ---------------------------------------
__global__ void k_edge_out(const float* __restrict__ E,
                           const float* __restrict__ beo,
                           const float* __restrict__ g2,
                           const float* __restrict__ b2,
                           float* __restrict__ out) {
    int w = blockIdx.x * 8 + (threadIdx.x >> 5);
    int lane = threadIdx.x & 31;
    int m = w & 255, n = (w >> 8) & 255, b = w >> 16;
    float am = d_am[w] * 0.5f;
    const float4* Er = (const float4*)&E[(size_t)w * EDGE_DIM];
    const float4* hn = (const float4*)&d_hp[(b * NN + n) * EDGE_DIM];
    const float4* hm = (const float4*)&d_hp[(b * NN + m) * EDGE_DIM];
    const float4* bo4 = (const float4*)beo;
    float4 x[2];
    float s = 0.f, s2 = 0.f;
    #pragma unroll
    for (int j = 0; j < 2; ++j) {
        int idx = j * 32 + lane;
        float4 e = Er[idx], a = hn[idx], cc = hm[idx], bb = bo4[idx];
        float4 v;
        v.x = e.x + am * (a.x + cc.x) + bb.x;
        v.y = e.y + am * (a.y + cc.y) + bb.y;
        v.z = e.z + am * (a.z + cc.z) + bb.z;
        v.w = e.w + am * (a.w + cc.w) + bb.w;
        x[j] = v;
        s  += v.x + v.y + v.z + v.w;
        s2 += v.x*v.x + v.y*v.y + v.z*v.z + v.w*v.w;
    }
    #pragma unroll
    for (int o = 16; o > 0; o >>= 1) {
        s  += __shfl_xor_sync(0xffffffffu, s,  o);
        s2 += __shfl_xor_sync(0xffffffffu, s2, o);
    }
    float mean = s * (1.f / EDGE_DIM);
    float var  = s2 * (1.f / EDGE_DIM) - mean * mean;
    float rinv = rsqrtf(var + LN_EPS);
    const float4* g4 = (const float4*)g2;
    const float4* b4 = (const float4*)b2;
    float4* op = (float4*)&out[OUT_EDGE_BASE + (size_t)w * EDGE_DIM];
    #pragma unroll
    for (int j = 0; j < 2; ++j) {
        int idx = j * 32 + lane;
        float4 g = g4[idx], bb = b4[idx], v = x[j], o4;
        o4.x = (v.x - mean) * rinv * g.x + bb.x;
        o4.y = (v.y - mean) * rinv * g.y + bb.y;
        o4.z = (v.z - mean) * rinv * g.z + bb.z;
        o4.w = (v.w - mean) * rinv * g.w + bb.w;
        op[idx] = o4;
    }
}

// ---------------- launch ------------------------------------------------------
extern "C" void kernel_launch(void* const* d_in, const int* in_sizes, int n_in,
                              void* d_out, int out_size) {
    const float* node = (const float*)d_in[0];
    const float* E    = (const float*)d_in[1];
    const int*   adj  = (const int*)  d_in[2];
    const float* Wn  = (const float*)d_in[3];  const float* bn  = (const float*)d_in[4];
    const float* Wq  = (const float*)d_in[5];  const float* bq  = (const float*)d_in[6];
    const float* Wk  = (const float*)d_in[7];  const float* bk  = (const float*)d_in[8];
    const float* Wv  = (const float*)d_in[9];  const float* bv  = (const float*)d_in[10];
    const float* Wep = (const float*)d_in[11]; const float* bep = (const float*)d_in[12];
    const float* Weg = (const float*)d_in[13]; const float* beg = (const float*)d_in[14];
    const float* Wo  = (const float*)d_in[15]; const float* bo  = (const float*)d_in[16];
    const float* Weo = (const float*)d_in[17]; const float* beo = (const float*)d_in[18];
    const float* g1  = (const float*)d_in[19]; const float* b1  = (const float*)d_in[20];
    const float* g2  = (const float*)d_in[21]; const float* b2  = (const float*)d_in[22];
    float* out = (float*)d_out;

    cudaFuncSetAttribute(k_edge_attn_mma, cudaFuncAttributeMaxDynamicSharedMemorySize, SMEM_BYTES);
    cudaFuncSetAttribute(k_qkv_f,    cudaFuncAttributeMaxDynamicSharedMemorySize, SM_GEMM);
    cudaFuncSetAttribute(k_node_f,   cudaFuncAttributeMaxDynamicSharedMemorySize, SM_NP);
    cudaFuncSetAttribute(k_hout_hp,  cudaFuncAttributeMaxDynamicSharedMemorySize, SM_HOUT);

    k_wT       <<<dim3(8, 8, 2), dim3(32, 32)>>>(Wep, Weg);
    k_node_f   <<<BB*NN/4 + NEH1, 256, SM_NP>>>(node, Wn, bn, E);
    k_qkv_f    <<<3*BB*NN/4 + NEH2, 256, SM_GEMM>>>(Wq, bq, Wk, bk, Wv, bv, E);
    k_scores_f <<<BB*HH*4 + NEH3, 256>>>(E);
    k_edge_attn_mma<<<dim3(HH, BB*NN), 256, SMEM_BYTES>>>(bep, beg, adj);
    k_attn_out <<<BB*128, 256>>>();
    k_hout_hp  <<<BB*NN/4, 256, SM_HOUT>>>(Wo, bo, g1, b1, Weo, out);
    k_edge_out <<<BB*NN*NN/8, 256>>>(E, beo, g2, b2, out);
}